// round 1
// baseline (speedup 1.0000x reference)
#include <cuda_runtime.h>
#include <cstdint>

#define NN 50000
#define EE 800000
#define DD 64
#define HH 4
#define FF 128
#define LL 2

// ---------------- device scratch (static, no allocation) ----------------
__device__ float g_Q[NN*DD];
__device__ float g_K[NN*DD];
__device__ float g_V[NN*DD];
__device__ float g_wV[NN*DD];
__device__ float g_Z[NN*HH];
__device__ float g_h[NN*DD];   // inter-layer h
__device__ float g_h1[NN*DD];  // post-LN1
__device__ float g_u[NN*FF];   // FFN hidden
__device__ int   g_is64;

// ---------------- index dtype detection (int64 vs int32) ----------------
__global__ void detect_idx_kernel(const long long* __restrict__ idx){
    if (blockIdx.x == 0 && threadIdx.x == 0){
        int ok = 1;
        #pragma unroll
        for (int i = 0; i < 16; i++){
            long long v = idx[i];
            if (v < 0 || v >= NN) ok = 0;
        }
        g_is64 = ok;
    }
}

// ---------------- zero accumulators ----------------
__global__ void zero_kernel(){
    int i = blockIdx.x * blockDim.x + threadIdx.x;
    if (i < NN*DD) g_wV[i] = 0.0f;
    if (i < NN*HH) g_Z[i]  = 0.0f;
}

// ---------------- Q,K,V projections: [N,64] @ 3x[64,64] ----------------
__global__ void __launch_bounds__(256) qkv_kernel(
        const float* __restrict__ h,
        const float* __restrict__ WQ,
        const float* __restrict__ WK,
        const float* __restrict__ WV){
    extern __shared__ float sm[];
    float* sQ = sm;
    float* sK = sm + DD*DD;
    float* sV = sm + 2*DD*DD;
    for (int i = threadIdx.x; i < DD*DD; i += 256){
        sQ[i] = WQ[i]; sK[i] = WK[i]; sV[i] = WV[i];
    }
    __syncthreads();
    const int j = threadIdx.x & 63;
    const int g = threadIdx.x >> 6;
    for (int n0 = blockIdx.x*4; n0 < NN; n0 += gridDim.x*4){
        const int n = n0 + g;
        const float* hr = h + (size_t)n*DD;
        float q = 0.f, k = 0.f, v = 0.f;
        #pragma unroll 8
        for (int i = 0; i < DD; i++){
            float hv = __ldg(hr + i);
            q = fmaf(hv, sQ[i*DD + j], q);
            k = fmaf(hv, sK[i*DD + j], k);
            v = fmaf(hv, sV[i*DD + j], v);
        }
        g_Q[(size_t)n*DD + j] = q;
        g_K[(size_t)n*DD + j] = k;
        g_V[(size_t)n*DD + j] = v;
    }
}

// ---------------- edge kernel: Eh GEMM + score + scatter ----------------
// 16 threads per edge, each owns a float4 of the 64 dims.
__global__ void __launch_bounds__(256) edge_kernel(
        const float* __restrict__ edge_attr,
        const void*  __restrict__ eidx,
        const float* __restrict__ WE){
    __shared__ float sWE[DD*DD];     // 16 KB
    __shared__ float sA[16][68];     // padded rows (bank-safe)
    for (int i = threadIdx.x; i < DD*DD; i += 256) sWE[i] = WE[i];
    __syncthreads();
    const int is64 = g_is64;
    const long long* p64 = (const long long*)eidx;
    const int*       p32 = (const int*)eidx;
    const int t  = threadIdx.x & 15;
    const int g  = threadIdx.x >> 4;
    const int t4 = t * 4;
    for (int e = blockIdx.x*16 + g; e < EE; e += gridDim.x*16){
        int src, dst;
        if (is64){ src = (int)p64[e]; dst = (int)p64[EE + e]; }
        else     { src = p32[e];      dst = p32[EE + e]; }
        // stage edge_attr row, prefetch gathers
        float4 a4 = *(const float4*)(edge_attr + (size_t)e*DD + t4);
        *(float4*)&sA[g][t4] = a4;
        float4 kk = *(const float4*)(g_K + (size_t)src*DD + t4);
        float4 qq = *(const float4*)(g_Q + (size_t)dst*DD + t4);
        float4 vv = *(const float4*)(g_V + (size_t)src*DD + t4);
        __syncwarp();
        // Eh[4t..4t+3] = A @ WE columns
        float4 eh = make_float4(0.f, 0.f, 0.f, 0.f);
        #pragma unroll 4
        for (int c = 0; c < DD; c += 4){
            float4 a  = *(const float4*)&sA[g][c];
            float4 w0 = *(const float4*)&sWE[(c+0)*DD + t4];
            float4 w1 = *(const float4*)&sWE[(c+1)*DD + t4];
            float4 w2 = *(const float4*)&sWE[(c+2)*DD + t4];
            float4 w3 = *(const float4*)&sWE[(c+3)*DD + t4];
            eh.x = fmaf(a.x, w0.x, fmaf(a.y, w1.x, fmaf(a.z, w2.x, fmaf(a.w, w3.x, eh.x))));
            eh.y = fmaf(a.x, w0.y, fmaf(a.y, w1.y, fmaf(a.z, w2.y, fmaf(a.w, w3.y, eh.y))));
            eh.z = fmaf(a.x, w0.z, fmaf(a.y, w1.z, fmaf(a.z, w2.z, fmaf(a.w, w3.z, eh.z))));
            eh.w = fmaf(a.x, w0.w, fmaf(a.y, w1.w, fmaf(a.z, w2.w, fmaf(a.w, w3.w, eh.w))));
        }
        // per-head score: 4 lanes (16 dims) per head
        float s = kk.x*qq.x*eh.x + kk.y*qq.y*eh.y + kk.z*qq.z*eh.z + kk.w*qq.w*eh.w;
        s += __shfl_xor_sync(0xffffffffu, s, 1);
        s += __shfl_xor_sync(0xffffffffu, s, 2);
        s *= 0.25f;                        // 1/sqrt(DH), DH=16
        s  = fminf(5.0f, fmaxf(-5.0f, s));
        float sc = expf(s);
        float* wb = g_wV + (size_t)dst*DD + t4;
        asm volatile("red.global.add.v4.f32 [%0], {%1, %2, %3, %4};"
                     :: "l"(wb), "f"(vv.x*sc), "f"(vv.y*sc), "f"(vv.z*sc), "f"(vv.w*sc)
                     : "memory");
        if ((t & 3) == 0){
            asm volatile("red.global.add.f32 [%0], %1;"
                         :: "l"(g_Z + (size_t)dst*HH + (t >> 2)), "f"(sc)
                         : "memory");
        }
        __syncwarp();
    }
}

// ---------------- combine: h_attn = wV/Z; h1 = LN(h + h_attn@WO + bO) ----------------
__global__ void __launch_bounds__(256) combine_kernel(
        const float* __restrict__ h_in,
        const float* __restrict__ WO,
        const float* __restrict__ bO,
        const float* __restrict__ lg,
        const float* __restrict__ lb){
    __shared__ float sW[DD*DD];
    __shared__ float sb[DD], sgm[DD], sbn[DD];
    __shared__ float sat[4][DD];
    __shared__ float sr1[4][DD];
    __shared__ float sr2[4][DD];
    for (int i = threadIdx.x; i < DD*DD; i += 256) sW[i] = WO[i];
    if (threadIdx.x < DD){
        sb[threadIdx.x]  = bO[threadIdx.x];
        sgm[threadIdx.x] = lg[threadIdx.x];
        sbn[threadIdx.x] = lb[threadIdx.x];
    }
    __syncthreads();
    const int j = threadIdx.x & 63;
    const int g = threadIdx.x >> 6;
    for (int n0 = blockIdx.x*4; n0 < NN; n0 += gridDim.x*4){
        const int n = n0 + g;
        float z  = g_Z[n*HH + (j >> 4)];
        float at = g_wV[(size_t)n*DD + j] / (z + 1e-6f);
        sat[g][j] = at;
        __syncthreads();
        float o = 0.f;
        #pragma unroll 8
        for (int i = 0; i < DD; i++) o = fmaf(sat[g][i], sW[i*DD + j], o);
        o += sb[j] + h_in[(size_t)n*DD + j];
        sr1[g][j] = o;
        sr2[g][j] = o * o;
        for (int sft = 32; sft > 0; sft >>= 1){
            __syncthreads();
            if (j < sft){ sr1[g][j] += sr1[g][j+sft]; sr2[g][j] += sr2[g][j+sft]; }
        }
        __syncthreads();
        float mu  = sr1[g][0] * (1.0f/DD);
        float var = sr2[g][0] * (1.0f/DD) - mu*mu;
        float inv = rsqrtf(var + 1e-5f);
        g_h1[(size_t)n*DD + j] = (o - mu) * inv * sgm[j] + sbn[j];
        __syncthreads();
    }
}

// ---------------- FFN fc1: u = relu(h1@W1 + b1), [N,128] ----------------
__global__ void __launch_bounds__(256) ffn1_kernel(
        const float* __restrict__ W1,
        const float* __restrict__ b1){
    __shared__ float sW[DD*FF];   // 32 KB
    __shared__ float sb[FF];
    __shared__ float sh[2][DD];
    for (int i = threadIdx.x; i < DD*FF; i += 256) sW[i] = W1[i];
    if (threadIdx.x < FF) sb[threadIdx.x] = b1[threadIdx.x];
    __syncthreads();
    const int j = threadIdx.x & 127;
    const int g = threadIdx.x >> 7;
    for (int n0 = blockIdx.x*2; n0 < NN; n0 += gridDim.x*2){
        const int n = n0 + g;
        if (j < DD) sh[g][j] = g_h1[(size_t)n*DD + j];
        __syncthreads();
        float acc = sb[j];
        #pragma unroll 8
        for (int i = 0; i < DD; i++) acc = fmaf(sh[g][i], sW[i*FF + j], acc);
        g_u[(size_t)n*FF + j] = fmaxf(acc, 0.0f);
        __syncthreads();
    }
}

// ---------------- FFN fc2 + residual + LN2 ----------------
__global__ void __launch_bounds__(256) ffn2_kernel(
        const float* __restrict__ W2,
        const float* __restrict__ b2,
        const float* __restrict__ lg,
        const float* __restrict__ lb,
        float* __restrict__ outp){
    __shared__ float sW[FF*DD];   // 32 KB
    __shared__ float sb[DD], sgm[DD], sbn[DD];
    __shared__ float su[4][FF];
    __shared__ float sr1[4][DD];
    __shared__ float sr2[4][DD];
    for (int i = threadIdx.x; i < FF*DD; i += 256) sW[i] = W2[i];
    if (threadIdx.x < DD){
        sb[threadIdx.x]  = b2[threadIdx.x];
        sgm[threadIdx.x] = lg[threadIdx.x];
        sbn[threadIdx.x] = lb[threadIdx.x];
    }
    __syncthreads();
    const int j = threadIdx.x & 63;
    const int g = threadIdx.x >> 6;
    for (int n0 = blockIdx.x*4; n0 < NN; n0 += gridDim.x*4){
        const int n = n0 + g;
        su[g][j]      = g_u[(size_t)n*FF + j];
        su[g][j + DD] = g_u[(size_t)n*FF + DD + j];
        __syncthreads();
        float o = 0.f;
        #pragma unroll 8
        for (int i = 0; i < FF; i++) o = fmaf(su[g][i], sW[i*DD + j], o);
        o += sb[j] + g_h1[(size_t)n*DD + j];
        sr1[g][j] = o;
        sr2[g][j] = o * o;
        for (int sft = 32; sft > 0; sft >>= 1){
            __syncthreads();
            if (j < sft){ sr1[g][j] += sr1[g][j+sft]; sr2[g][j] += sr2[g][j+sft]; }
        }
        __syncthreads();
        float mu  = sr1[g][0] * (1.0f/DD);
        float var = sr2[g][0] * (1.0f/DD) - mu*mu;
        float inv = rsqrtf(var + 1e-5f);
        outp[(size_t)n*DD + j] = (o - mu) * inv * sgm[j] + sbn[j];
        __syncthreads();
    }
}

// ---------------- host launcher ----------------
extern "C" void kernel_launch(void* const* d_in, const int* in_sizes, int n_in,
                              void* d_out, int out_size){
    const float* x   = (const float*)d_in[0];
    const float* ea  = (const float*)d_in[1];
    const void*  ei  = d_in[2];
    const float* WQ  = (const float*)d_in[3];
    const float* WK  = (const float*)d_in[4];
    const float* WE  = (const float*)d_in[5];
    const float* WV  = (const float*)d_in[6];
    const float* WO  = (const float*)d_in[7];
    const float* bO  = (const float*)d_in[8];
    const float* g1  = (const float*)d_in[9];
    const float* b1n = (const float*)d_in[10];
    const float* W1  = (const float*)d_in[11];
    const float* b1  = (const float*)d_in[12];
    const float* W2  = (const float*)d_in[13];
    const float* b2  = (const float*)d_in[14];
    const float* g2  = (const float*)d_in[15];
    const float* b2n = (const float*)d_in[16];
    float* outp = (float*)d_out;

    float* p_h = nullptr;
    cudaGetSymbolAddress((void**)&p_h, g_h);

    cudaFuncSetAttribute(qkv_kernel,
                         cudaFuncAttributeMaxDynamicSharedMemorySize,
                         3*DD*DD*(int)sizeof(float));

    detect_idx_kernel<<<1, 1>>>((const long long*)ei);

    for (int l = 0; l < LL; l++){
        const float* hin  = (l == 0) ? x : (const float*)p_h;
        float*       hout = (l == LL-1) ? outp : p_h;
        qkv_kernel<<<592, 256, 3*DD*DD*sizeof(float)>>>(
            hin, WQ + l*DD*DD, WK + l*DD*DD, WV + l*DD*DD);
        zero_kernel<<<(NN*DD + 255)/256, 256>>>();
        edge_kernel<<<1480, 256>>>(ea, ei, WE + l*DD*DD);
        combine_kernel<<<1184, 256>>>(hin, WO + l*DD*DD, bO + l*DD,
                                      g1 + l*DD, b1n + l*DD);
        ffn1_kernel<<<1184, 256>>>(W1 + l*DD*FF, b1 + l*FF);
        ffn2_kernel<<<1184, 256>>>(W2 + l*FF*DD, b2 + l*DD,
                                   g2 + l*DD, b2n + l*DD, hout);
    }
}

// round 3
// speedup vs baseline: 1.5136x; 1.5136x over previous
#include <cuda_runtime.h>
#include <cstdint>

#define NN 50000
#define EE 800000
#define DD 64
#define HH 4
#define FF 128
#define LL 2

#define ASTR 68
#define BSTR 72

// ---------------- device scratch (static, no allocation) ----------------
__device__ float g_Q[NN*DD];
__device__ float g_K[NN*DD];
__device__ float g_V[NN*DD];
__device__ float g_wV[NN*DD];
__device__ float g_Z[NN*HH];
__device__ float g_h[NN*DD];    // inter-layer h
__device__ float g_h1[NN*DD];   // post-LN1
__device__ float g_u[NN*FF];    // FFN hidden
__device__ float g_Eh[(size_t)EE*DD];  // materialized edge projections (205 MB)
__device__ int   g_is64;

// ---------------- tf32 helpers ----------------
__device__ __forceinline__ void split_tf32(float x, uint32_t& hi, uint32_t& lo){
    asm("cvt.rna.tf32.f32 %0, %1;" : "=r"(hi) : "f"(x));
    float r = x - __uint_as_float(hi);
    asm("cvt.rna.tf32.f32 %0, %1;" : "=r"(lo) : "f"(r));
}
__device__ __forceinline__ void mma8(float* c, const uint32_t* a, uint32_t b0, uint32_t b1){
    asm volatile(
      "mma.sync.aligned.m16n8k8.row.col.f32.tf32.tf32.f32 "
      "{%0,%1,%2,%3}, {%4,%5,%6,%7}, {%8,%9}, {%0,%1,%2,%3};"
      : "+f"(c[0]), "+f"(c[1]), "+f"(c[2]), "+f"(c[3])
      : "r"(a[0]), "r"(a[1]), "r"(a[2]), "r"(a[3]), "r"(b0), "r"(b1));
}

// ---------------- index dtype detection (int64 vs int32) ----------------
__global__ void detect_idx_kernel(const long long* __restrict__ idx){
    if (blockIdx.x == 0 && threadIdx.x == 0){
        int ok = 1;
        #pragma unroll
        for (int i = 0; i < 16; i++){
            long long v = idx[i];
            if (v < 0 || v >= NN) ok = 0;
        }
        g_is64 = ok;
    }
}

// ---------------- zero accumulators ----------------
__global__ void zero_kernel(){
    int i = blockIdx.x * blockDim.x + threadIdx.x;
    if (i < NN*DD) g_wV[i] = 0.0f;
    if (i < NN*HH) g_Z[i]  = 0.0f;
}

// ================= generic [M,64]@[64,64] 3xTF32 MMA GEMM ================
// Block: 256 threads (8 warps), 128 rows/block. Each warp: 16 rows x 64 cols.
__device__ __forceinline__ void gemm_tile_compute(
        const float* sA, const float* sBh, const float* sBl,
        int warp, int lane, float c[8][4]){
    const int gID = lane >> 2, tig = lane & 3;
    const int wr = warp * 16;
    #pragma unroll
    for (int nt = 0; nt < 8; nt++){ c[nt][0]=c[nt][1]=c[nt][2]=c[nt][3]=0.f; }
    #pragma unroll
    for (int k = 0; k < 8; k++){
        const float* ap = sA + (wr + gID)*ASTR + k*8 + tig;
        float a0f = ap[0], a1f = ap[8*ASTR], a2f = ap[4], a3f = ap[8*ASTR + 4];
        uint32_t ah[4], al[4];
        split_tf32(a0f, ah[0], al[0]);
        split_tf32(a1f, ah[1], al[1]);
        split_tf32(a2f, ah[2], al[2]);
        split_tf32(a3f, ah[3], al[3]);
        const int brow = k*8 + tig;
        #pragma unroll
        for (int nt = 0; nt < 8; nt++){
            const int bc = nt*8 + gID;
            uint32_t bh0 = __float_as_uint(sBh[brow*BSTR + bc]);
            uint32_t bh1 = __float_as_uint(sBh[(brow+4)*BSTR + bc]);
            uint32_t bl0 = __float_as_uint(sBl[brow*BSTR + bc]);
            uint32_t bl1 = __float_as_uint(sBl[(brow+4)*BSTR + bc]);
            mma8(c[nt], ah, bh0, bh1);   // hi*hi
            mma8(c[nt], ah, bl0, bl1);   // hi*lo
            mma8(c[nt], al, bh0, bh1);   // lo*hi
        }
    }
}

__device__ __forceinline__ void gemm_store(
        float* __restrict__ C, int m0, int M, int warp, int lane, float c[8][4]){
    const int gID = lane >> 2, tig = lane & 3;
    const int r0 = m0 + warp*16 + gID;
    const int r1 = r0 + 8;
    #pragma unroll
    for (int nt = 0; nt < 8; nt++){
        const int col = nt*8 + tig*2;
        if (r0 < M) *(float2*)&C[(size_t)r0*DD + col] = make_float2(c[nt][0], c[nt][1]);
        if (r1 < M) *(float2*)&C[(size_t)r1*DD + col] = make_float2(c[nt][2], c[nt][3]);
    }
}

// Eh = edge_attr @ WE
__global__ void __launch_bounds__(256) gemm64_kernel(
        const float* __restrict__ A, const float* __restrict__ B,
        float* __restrict__ C, int M){
    extern __shared__ float sm[];
    float* sA  = sm;                    // 128 x ASTR
    float* sBh = sm + 128*ASTR;         // 64 x BSTR
    float* sBl = sBh + 64*BSTR;
    const int tid = threadIdx.x;
    const int m0 = blockIdx.x * 128;
    for (int i = tid; i < 128*64; i += 256){
        int r = i >> 6, cc = i & 63;
        float v = (m0 + r < M) ? A[(size_t)(m0+r)*DD + cc] : 0.f;
        sA[r*ASTR + cc] = v;
    }
    for (int i = tid; i < 64*64; i += 256){
        int r = i >> 6, cc = i & 63;
        uint32_t h, l; split_tf32(B[i], h, l);
        sBh[r*BSTR + cc] = __uint_as_float(h);
        sBl[r*BSTR + cc] = __uint_as_float(l);
    }
    __syncthreads();
    const int warp = tid >> 5, lane = tid & 31;
    float c[8][4];
    gemm_tile_compute(sA, sBh, sBl, warp, lane, c);
    gemm_store(C, m0, M, warp, lane, c);
}

// Q,K,V = h @ {WQ,WK,WV}  (shared A tile, loop over 3 weights)
__global__ void __launch_bounds__(256) qkv_mma_kernel(
        const float* __restrict__ A,
        const float* __restrict__ WQ, const float* __restrict__ WK,
        const float* __restrict__ WV, int M){
    extern __shared__ float sm[];
    float* sA  = sm;
    float* sBh = sm + 128*ASTR;
    float* sBl = sBh + 64*BSTR;
    const int tid = threadIdx.x;
    const int m0 = blockIdx.x * 128;
    for (int i = tid; i < 128*64; i += 256){
        int r = i >> 6, cc = i & 63;
        float v = (m0 + r < M) ? A[(size_t)(m0+r)*DD + cc] : 0.f;
        sA[r*ASTR + cc] = v;
    }
    const int warp = tid >> 5, lane = tid & 31;
    #pragma unroll
    for (int w = 0; w < 3; w++){
        const float* B = (w == 0) ? WQ : (w == 1) ? WK : WV;
        float* C = (w == 0) ? g_Q : (w == 1) ? g_K : g_V;
        __syncthreads();   // previous compute done reading sB (and sA ready on w=0)
        for (int i = tid; i < 64*64; i += 256){
            int r = i >> 6, cc = i & 63;
            uint32_t h, l; split_tf32(B[i], h, l);
            sBh[r*BSTR + cc] = __uint_as_float(h);
            sBl[r*BSTR + cc] = __uint_as_float(l);
        }
        __syncthreads();
        float c[8][4];
        gemm_tile_compute(sA, sBh, sBl, warp, lane, c);
        gemm_store(C, m0, M, warp, lane, c);
    }
}

// ---------------- lean edge kernel: gather + score + scatter ----------------
__global__ void __launch_bounds__(256) edge_kernel(const void* __restrict__ eidx){
    const int is64 = g_is64;
    const long long* p64 = (const long long*)eidx;
    const int*       p32 = (const int*)eidx;
    const int t  = threadIdx.x & 15;
    const int g  = threadIdx.x >> 4;
    const int t4 = t * 4;
    for (int e = blockIdx.x*16 + g; e < EE; e += gridDim.x*16){
        int src, dst;
        if (is64){ src = (int)p64[e]; dst = (int)p64[EE + e]; }
        else     { src = p32[e];      dst = p32[EE + e]; }
        float4 eh = *(const float4*)(g_Eh + (size_t)e*DD + t4);
        float4 kk = *(const float4*)(g_K + (size_t)src*DD + t4);
        float4 qq = *(const float4*)(g_Q + (size_t)dst*DD + t4);
        float4 vv = *(const float4*)(g_V + (size_t)src*DD + t4);
        float s = kk.x*qq.x*eh.x + kk.y*qq.y*eh.y + kk.z*qq.z*eh.z + kk.w*qq.w*eh.w;
        s += __shfl_xor_sync(0xffffffffu, s, 1);
        s += __shfl_xor_sync(0xffffffffu, s, 2);
        s *= 0.25f;                        // 1/sqrt(16)
        s  = fminf(5.0f, fmaxf(-5.0f, s));
        float sc = expf(s);
        float* wb = g_wV + (size_t)dst*DD + t4;
        asm volatile("red.global.add.v4.f32 [%0], {%1, %2, %3, %4};"
                     :: "l"(wb), "f"(vv.x*sc), "f"(vv.y*sc), "f"(vv.z*sc), "f"(vv.w*sc)
                     : "memory");
        if ((t & 3) == 0){
            asm volatile("red.global.add.f32 [%0], %1;"
                         :: "l"(g_Z + (size_t)dst*HH + (t >> 2)), "f"(sc)
                         : "memory");
        }
    }
}

// ---------------- combine: h_attn = wV/Z; h1 = LN(h + h_attn@WO + bO) ----------------
__global__ void __launch_bounds__(256) combine_kernel(
        const float* __restrict__ h_in,
        const float* __restrict__ WO,
        const float* __restrict__ bO,
        const float* __restrict__ lg,
        const float* __restrict__ lb){
    __shared__ float sW[DD*DD];
    __shared__ float sb[DD], sgm[DD], sbn[DD];
    __shared__ float sat[2][4][DD];
    __shared__ float xch[2][4][2][2];
    for (int i = threadIdx.x; i < DD*DD; i += 256) sW[i] = WO[i];
    if (threadIdx.x < DD){
        sb[threadIdx.x]  = bO[threadIdx.x];
        sgm[threadIdx.x] = lg[threadIdx.x];
        sbn[threadIdx.x] = lb[threadIdx.x];
    }
    __syncthreads();
    const int j = threadIdx.x & 63;
    const int g = threadIdx.x >> 6;
    const int w = (threadIdx.x >> 5) & 1;
    const int lane = threadIdx.x & 31;
    int p = 0;
    for (int n0 = blockIdx.x*4; n0 < NN; n0 += gridDim.x*4){
        const int n = n0 + g;
        float z  = g_Z[n*HH + (j >> 4)];
        sat[p][g][j] = g_wV[(size_t)n*DD + j] / (z + 1e-6f);
        __syncthreads();
        float o = 0.f;
        #pragma unroll 8
        for (int i = 0; i < DD; i++) o = fmaf(sat[p][g][i], sW[i*DD + j], o);
        o += sb[j] + h_in[(size_t)n*DD + j];
        float s1 = o, s2 = o*o;
        #pragma unroll
        for (int off = 16; off > 0; off >>= 1){
            s1 += __shfl_xor_sync(0xffffffffu, s1, off);
            s2 += __shfl_xor_sync(0xffffffffu, s2, off);
        }
        if (lane == 0){ xch[p][g][w][0] = s1; xch[p][g][w][1] = s2; }
        __syncthreads();
        float m1 = xch[p][g][0][0] + xch[p][g][1][0];
        float m2 = xch[p][g][0][1] + xch[p][g][1][1];
        float mu  = m1 * (1.0f/DD);
        float var = m2 * (1.0f/DD) - mu*mu;
        float inv = rsqrtf(var + 1e-5f);
        g_h1[(size_t)n*DD + j] = (o - mu) * inv * sgm[j] + sbn[j];
        p ^= 1;
    }
}

// ---------------- FFN fc1: u = relu(h1@W1 + b1), [N,128] ----------------
__global__ void __launch_bounds__(256) ffn1_kernel(
        const float* __restrict__ W1,
        const float* __restrict__ b1){
    __shared__ float sW[DD*FF];   // 32 KB
    __shared__ float sb[FF];
    __shared__ float sh[2][2][DD];
    for (int i = threadIdx.x; i < DD*FF; i += 256) sW[i] = W1[i];
    if (threadIdx.x < FF) sb[threadIdx.x] = b1[threadIdx.x];
    __syncthreads();
    const int j = threadIdx.x & 127;
    const int g = threadIdx.x >> 7;
    int p = 0;
    for (int n0 = blockIdx.x*2; n0 < NN; n0 += gridDim.x*2){
        const int n = n0 + g;
        if (j < DD) sh[p][g][j] = g_h1[(size_t)n*DD + j];
        __syncthreads();
        float acc = sb[j];
        #pragma unroll 8
        for (int i = 0; i < DD; i++) acc = fmaf(sh[p][g][i], sW[i*FF + j], acc);
        g_u[(size_t)n*FF + j] = fmaxf(acc, 0.0f);
        p ^= 1;
    }
}

// ---------------- FFN fc2 + residual + LN2 ----------------
__global__ void __launch_bounds__(256) ffn2_kernel(
        const float* __restrict__ W2,
        const float* __restrict__ b2,
        const float* __restrict__ lg,
        const float* __restrict__ lb,
        float* __restrict__ outp){
    __shared__ float sW[FF*DD];   // 32 KB
    __shared__ float sb[DD], sgm[DD], sbn[DD];
    __shared__ float su[2][4][FF];
    __shared__ float xch[2][4][2][2];
    for (int i = threadIdx.x; i < FF*DD; i += 256) sW[i] = W2[i];
    if (threadIdx.x < DD){
        sb[threadIdx.x]  = b2[threadIdx.x];
        sgm[threadIdx.x] = lg[threadIdx.x];
        sbn[threadIdx.x] = lb[threadIdx.x];
    }
    __syncthreads();
    const int j = threadIdx.x & 63;
    const int g = threadIdx.x >> 6;
    const int w = (threadIdx.x >> 5) & 1;
    const int lane = threadIdx.x & 31;
    int p = 0;
    for (int n0 = blockIdx.x*4; n0 < NN; n0 += gridDim.x*4){
        const int n = n0 + g;
        su[p][g][j]      = g_u[(size_t)n*FF + j];
        su[p][g][j + DD] = g_u[(size_t)n*FF + DD + j];
        __syncthreads();
        float o = 0.f;
        #pragma unroll 8
        for (int i = 0; i < FF; i++) o = fmaf(su[p][g][i], sW[i*DD + j], o);
        o += sb[j] + g_h1[(size_t)n*DD + j];
        float s1 = o, s2 = o*o;
        #pragma unroll
        for (int off = 16; off > 0; off >>= 1){
            s1 += __shfl_xor_sync(0xffffffffu, s1, off);
            s2 += __shfl_xor_sync(0xffffffffu, s2, off);
        }
        if (lane == 0){ xch[p][g][w][0] = s1; xch[p][g][w][1] = s2; }
        __syncthreads();
        float m1 = xch[p][g][0][0] + xch[p][g][1][0];
        float m2 = xch[p][g][0][1] + xch[p][g][1][1];
        float mu  = m1 * (1.0f/DD);
        float var = m2 * (1.0f/DD) - mu*mu;
        float inv = rsqrtf(var + 1e-5f);
        outp[(size_t)n*DD + j] = (o - mu) * inv * sgm[j] + sbn[j];
        p ^= 1;
    }
}

// ---------------- host launcher ----------------
extern "C" void kernel_launch(void* const* d_in, const int* in_sizes, int n_in,
                              void* d_out, int out_size){
    const float* x   = (const float*)d_in[0];
    const float* ea  = (const float*)d_in[1];
    const void*  ei  = d_in[2];
    const float* WQ  = (const float*)d_in[3];
    const float* WK  = (const float*)d_in[4];
    const float* WE  = (const float*)d_in[5];
    const float* WV  = (const float*)d_in[6];
    const float* WO  = (const float*)d_in[7];
    const float* bO  = (const float*)d_in[8];
    const float* g1  = (const float*)d_in[9];
    const float* b1n = (const float*)d_in[10];
    const float* W1  = (const float*)d_in[11];
    const float* b1  = (const float*)d_in[12];
    const float* W2  = (const float*)d_in[13];
    const float* b2  = (const float*)d_in[14];
    const float* g2  = (const float*)d_in[15];
    const float* b2n = (const float*)d_in[16];
    float* outp = (float*)d_out;

    float* p_h = nullptr;
    float* p_Eh = nullptr;
    cudaGetSymbolAddress((void**)&p_h, g_h);
    cudaGetSymbolAddress((void**)&p_Eh, g_Eh);

    const int gemm_smem = (128*ASTR + 2*64*BSTR) * (int)sizeof(float);  // ~70 KB
    cudaFuncSetAttribute(gemm64_kernel,
                         cudaFuncAttributeMaxDynamicSharedMemorySize, gemm_smem);
    cudaFuncSetAttribute(qkv_mma_kernel,
                         cudaFuncAttributeMaxDynamicSharedMemorySize, gemm_smem);

    detect_idx_kernel<<<1, 1>>>((const long long*)ei);

    const int eh_blocks  = (EE + 127) / 128;   // 6250
    const int qkv_blocks = (NN + 127) / 128;   // 391

    for (int l = 0; l < LL; l++){
        const float* hin  = (l == 0) ? x : (const float*)p_h;
        float*       hout = (l == LL-1) ? outp : p_h;
        qkv_mma_kernel<<<qkv_blocks, 256, gemm_smem>>>(
            hin, WQ + l*DD*DD, WK + l*DD*DD, WV + l*DD*DD, NN);
        gemm64_kernel<<<eh_blocks, 256, gemm_smem>>>(
            ea, WE + l*DD*DD, p_Eh, EE);
        zero_kernel<<<(NN*DD + 255)/256, 256>>>();
        edge_kernel<<<2960, 256>>>(ei);
        combine_kernel<<<1184, 256>>>(hin, WO + l*DD*DD, bO + l*DD,
                                      g1 + l*DD, b1n + l*DD);
        ffn1_kernel<<<1184, 256>>>(W1 + l*DD*FF, b1 + l*FF);
        ffn2_kernel<<<1184, 256>>>(W2 + l*FF*DD, b2 + l*DD,
                                   g2 + l*DD, b2n + l*DD, hout);
    }
}

// round 6
// speedup vs baseline: 1.6241x; 1.0730x over previous
#include <cuda_runtime.h>
#include <cstdint>

#define NN 50000
#define EE 800000
#define DD 64
#define HH 4
#define FF 128
#define LL 2

#define ASTR 68
#define BSTR 72

// ---------------- device scratch (static, no allocation) ----------------
__device__ float g_Q[NN*DD];
__device__ float g_K[NN*DD];
__device__ float g_V[NN*DD];
__device__ float g_wV[NN*DD];
__device__ float g_Z[NN*HH];
__device__ float g_h[NN*DD];    // inter-layer h
__device__ float g_h1[NN*DD];   // post-LN1
__device__ float g_u[NN*FF];    // FFN hidden
__device__ int   g_is64;

// ---------------- tf32 helpers ----------------
__device__ __forceinline__ void split_tf32(float x, uint32_t& hi, uint32_t& lo){
    asm("cvt.rna.tf32.f32 %0, %1;" : "=r"(hi) : "f"(x));
    float r = x - __uint_as_float(hi);
    asm("cvt.rna.tf32.f32 %0, %1;" : "=r"(lo) : "f"(r));
}
__device__ __forceinline__ void mma8(float* c, const uint32_t* a, uint32_t b0, uint32_t b1){
    asm volatile(
      "mma.sync.aligned.m16n8k8.row.col.f32.tf32.tf32.f32 "
      "{%0,%1,%2,%3}, {%4,%5,%6,%7}, {%8,%9}, {%0,%1,%2,%3};"
      : "+f"(c[0]), "+f"(c[1]), "+f"(c[2]), "+f"(c[3])
      : "r"(a[0]), "r"(a[1]), "r"(a[2]), "r"(a[3]), "r"(b0), "r"(b1));
}

// ---------------- index dtype detection (int64 vs int32) ----------------
__global__ void detect_idx_kernel(const long long* __restrict__ idx){
    if (blockIdx.x == 0 && threadIdx.x == 0){
        int ok = 1;
        #pragma unroll
        for (int i = 0; i < 16; i++){
            long long v = idx[i];
            if (v < 0 || v >= NN) ok = 0;
        }
        g_is64 = ok;
    }
}

// ---------------- zero accumulators (vectorized) ----------------
__global__ void zero_kernel(){
    int i = blockIdx.x * blockDim.x + threadIdx.x;
    if (i < NN*DD/4) ((float4*)g_wV)[i] = make_float4(0.f,0.f,0.f,0.f);
    if (i < NN*HH/4) ((float4*)g_Z)[i]  = make_float4(0.f,0.f,0.f,0.f);
}

// ================= MMA tile compute: [128,64]@[64,64], 3xTF32 ============
__device__ __forceinline__ void gemm_tile_compute(
        const float* sA, const float* sBh, const float* sBl,
        int warp, int lane, float c[8][4]){
    const int gID = lane >> 2, tig = lane & 3;
    const int wr = warp * 16;
    #pragma unroll
    for (int nt = 0; nt < 8; nt++){ c[nt][0]=c[nt][1]=c[nt][2]=c[nt][3]=0.f; }
    #pragma unroll
    for (int k = 0; k < 8; k++){
        const float* ap = sA + (wr + gID)*ASTR + k*8 + tig;
        float a0f = ap[0], a1f = ap[8*ASTR], a2f = ap[4], a3f = ap[8*ASTR + 4];
        uint32_t ah[4], al[4];
        split_tf32(a0f, ah[0], al[0]);
        split_tf32(a1f, ah[1], al[1]);
        split_tf32(a2f, ah[2], al[2]);
        split_tf32(a3f, ah[3], al[3]);
        const int brow = k*8 + tig;
        #pragma unroll
        for (int nt = 0; nt < 8; nt++){
            const int bc = nt*8 + gID;
            uint32_t bh0 = __float_as_uint(sBh[brow*BSTR + bc]);
            uint32_t bh1 = __float_as_uint(sBh[(brow+4)*BSTR + bc]);
            uint32_t bl0 = __float_as_uint(sBl[brow*BSTR + bc]);
            uint32_t bl1 = __float_as_uint(sBl[(brow+4)*BSTR + bc]);
            mma8(c[nt], ah, bh0, bh1);   // hi*hi
            mma8(c[nt], ah, bl0, bl1);   // hi*lo
            mma8(c[nt], al, bh0, bh1);   // lo*hi
        }
    }
}

__device__ __forceinline__ void gemm_store(
        float* __restrict__ C, int m0, int M, int warp, int lane, float c[8][4]){
    const int gID = lane >> 2, tig = lane & 3;
    const int r0 = m0 + warp*16 + gID;
    const int r1 = r0 + 8;
    #pragma unroll
    for (int nt = 0; nt < 8; nt++){
        const int col = nt*8 + tig*2;
        if (r0 < M) *(float2*)&C[(size_t)r0*DD + col] = make_float2(c[nt][0], c[nt][1]);
        if (r1 < M) *(float2*)&C[(size_t)r1*DD + col] = make_float2(c[nt][2], c[nt][3]);
    }
}

// ========== FUSED: Eh = edge_attr@WE, then score + scatter (no g_Eh) =====
__global__ void __launch_bounds__(256) edge_fused_kernel(
        const float* __restrict__ A,        // edge_attr
        const float* __restrict__ B,        // WE
        const void*  __restrict__ eidx){
    extern __shared__ float sm[];
    float* sA  = sm;                    // 128 x ASTR (edge_attr, later Eh)
    float* sBh = sm + 128*ASTR;         // 64 x BSTR
    float* sBl = sBh + 64*BSTR;
    const int tid = threadIdx.x;
    const int m0 = blockIdx.x * 128;    // EE % 128 == 0: no tail
    for (int i = tid; i < 128*64; i += 256){
        int r = i >> 6, cc = i & 63;
        sA[r*ASTR + cc] = A[(size_t)(m0+r)*DD + cc];
    }
    for (int i = tid; i < 64*64; i += 256){
        int r = i >> 6, cc = i & 63;
        uint32_t h, l; split_tf32(B[i], h, l);
        sBh[r*BSTR + cc] = __uint_as_float(h);
        sBl[r*BSTR + cc] = __uint_as_float(l);
    }
    __syncthreads();
    const int warp = tid >> 5, lane = tid & 31;
    float c[8][4];
    gemm_tile_compute(sA, sBh, sBl, warp, lane, c);
    __syncthreads();   // done reading sA (edge_attr); safe to overwrite with Eh
    {
        const int gID = lane >> 2, tig = lane & 3;
        const int r0 = warp*16 + gID;
        const int r1 = r0 + 8;
        #pragma unroll
        for (int nt = 0; nt < 8; nt++){
            const int col = nt*8 + tig*2;
            *(float2*)&sA[r0*ASTR + col] = make_float2(c[nt][0], c[nt][1]);
            *(float2*)&sA[r1*ASTR + col] = make_float2(c[nt][2], c[nt][3]);
        }
    }
    __syncthreads();
    // ---- epilogue: 16 threads/edge, 8 iterations over 128 edges ----
    const int is64 = g_is64;
    const long long* p64 = (const long long*)eidx;
    const int*       p32 = (const int*)eidx;
    const int t  = tid & 15;
    const int g  = tid >> 4;
    const int t4 = t * 4;
    // preload indices for all 8 iterations (branch hoisted out of hot loop)
    int srcs[8], dsts[8];
    #pragma unroll
    for (int it = 0; it < 8; it++){
        const int e = m0 + it*16 + g;
        if (is64){ srcs[it] = (int)p64[e]; dsts[it] = (int)p64[EE + e]; }
        else     { srcs[it] = p32[e];      dsts[it] = p32[EE + e]; }
    }
    #pragma unroll
    for (int it = 0; it < 8; it++){
        const int le  = it*16 + g;
        const int src = srcs[it], dst = dsts[it];
        float4 eh = *(const float4*)&sA[le*ASTR + t4];
        float4 kk = *(const float4*)(g_K + (size_t)src*DD + t4);
        float4 qq = *(const float4*)(g_Q + (size_t)dst*DD + t4);
        float4 vv = *(const float4*)(g_V + (size_t)src*DD + t4);
        float s = kk.x*qq.x*eh.x + kk.y*qq.y*eh.y + kk.z*qq.z*eh.z + kk.w*qq.w*eh.w;
        s += __shfl_xor_sync(0xffffffffu, s, 1);
        s += __shfl_xor_sync(0xffffffffu, s, 2);
        s *= 0.25f;                        // 1/sqrt(16)
        s  = fminf(5.0f, fmaxf(-5.0f, s));
        float sc = expf(s);
        float* wb = g_wV + (size_t)dst*DD + t4;
        asm volatile("red.global.add.v4.f32 [%0], {%1, %2, %3, %4};"
                     :: "l"(wb), "f"(vv.x*sc), "f"(vv.y*sc), "f"(vv.z*sc), "f"(vv.w*sc)
                     : "memory");
        if ((t & 3) == 0){
            asm volatile("red.global.add.f32 [%0], %1;"
                         :: "l"(g_Z + (size_t)dst*HH + (t >> 2)), "f"(sc)
                         : "memory");
        }
    }
}

// Q,K,V = h @ {WQ,WK,WV}  (shared A tile, loop over 3 weights)
__global__ void __launch_bounds__(256) qkv_mma_kernel(
        const float* __restrict__ A,
        const float* __restrict__ WQ, const float* __restrict__ WK,
        const float* __restrict__ WV, int M){
    extern __shared__ float sm[];
    float* sA  = sm;
    float* sBh = sm + 128*ASTR;
    float* sBl = sBh + 64*BSTR;
    const int tid = threadIdx.x;
    const int m0 = blockIdx.x * 128;
    for (int i = tid; i < 128*64; i += 256){
        int r = i >> 6, cc = i & 63;
        float v = (m0 + r < M) ? A[(size_t)(m0+r)*DD + cc] : 0.f;
        sA[r*ASTR + cc] = v;
    }
    const int warp = tid >> 5, lane = tid & 31;
    #pragma unroll
    for (int w = 0; w < 3; w++){
        const float* B = (w == 0) ? WQ : (w == 1) ? WK : WV;
        float* C = (w == 0) ? g_Q : (w == 1) ? g_K : g_V;
        __syncthreads();
        for (int i = tid; i < 64*64; i += 256){
            int r = i >> 6, cc = i & 63;
            uint32_t h, l; split_tf32(B[i], h, l);
            sBh[r*BSTR + cc] = __uint_as_float(h);
            sBl[r*BSTR + cc] = __uint_as_float(l);
        }
        __syncthreads();
        float c[8][4];
        gemm_tile_compute(sA, sBh, sBl, warp, lane, c);
        gemm_store(C, m0, M, warp, lane, c);
    }
}

// ---------------- combine: h_attn = wV/Z; h1 = LN(h + h_attn@WO + bO) ----------------
__global__ void __launch_bounds__(256) combine_kernel(
        const float* __restrict__ h_in,
        const float* __restrict__ WO,
        const float* __restrict__ bO,
        const float* __restrict__ lg,
        const float* __restrict__ lb){
    __shared__ float sW[DD*DD];
    __shared__ float sb[DD], sgm[DD], sbn[DD];
    __shared__ float sat[2][4][DD];
    __shared__ float xch[2][4][2][2];
    for (int i = threadIdx.x; i < DD*DD; i += 256) sW[i] = WO[i];
    if (threadIdx.x < DD){
        sb[threadIdx.x]  = bO[threadIdx.x];
        sgm[threadIdx.x] = lg[threadIdx.x];
        sbn[threadIdx.x] = lb[threadIdx.x];
    }
    __syncthreads();
    const int j = threadIdx.x & 63;
    const int g = threadIdx.x >> 6;
    const int w = (threadIdx.x >> 5) & 1;
    const int lane = threadIdx.x & 31;
    int p = 0;
    for (int n0 = blockIdx.x*4; n0 < NN; n0 += gridDim.x*4){
        const int n = n0 + g;
        float z  = g_Z[n*HH + (j >> 4)];
        sat[p][g][j] = g_wV[(size_t)n*DD + j] / (z + 1e-6f);
        __syncthreads();
        float o = 0.f;
        #pragma unroll 8
        for (int i = 0; i < DD; i++) o = fmaf(sat[p][g][i], sW[i*DD + j], o);
        o += sb[j] + h_in[(size_t)n*DD + j];
        float s1 = o, s2 = o*o;
        #pragma unroll
        for (int off = 16; off > 0; off >>= 1){
            s1 += __shfl_xor_sync(0xffffffffu, s1, off);
            s2 += __shfl_xor_sync(0xffffffffu, s2, off);
        }
        if (lane == 0){ xch[p][g][w][0] = s1; xch[p][g][w][1] = s2; }
        __syncthreads();
        float m1 = xch[p][g][0][0] + xch[p][g][1][0];
        float m2 = xch[p][g][0][1] + xch[p][g][1][1];
        float mu  = m1 * (1.0f/DD);
        float var = m2 * (1.0f/DD) - mu*mu;
        float inv = rsqrtf(var + 1e-5f);
        g_h1[(size_t)n*DD + j] = (o - mu) * inv * sgm[j] + sbn[j];
        p ^= 1;
    }
}

// ---------------- FFN fc1: u = relu(h1@W1 + b1), [N,128] ----------------
__global__ void __launch_bounds__(256) ffn1_kernel(
        const float* __restrict__ W1,
        const float* __restrict__ b1){
    __shared__ float sW[DD*FF];   // 32 KB
    __shared__ float sb[FF];
    __shared__ float sh[2][2][DD];
    for (int i = threadIdx.x; i < DD*FF; i += 256) sW[i] = W1[i];
    if (threadIdx.x < FF) sb[threadIdx.x] = b1[threadIdx.x];
    __syncthreads();
    const int j = threadIdx.x & 127;
    const int g = threadIdx.x >> 7;
    int p = 0;
    for (int n0 = blockIdx.x*2; n0 < NN; n0 += gridDim.x*2){
        const int n = n0 + g;
        if (j < DD) sh[p][g][j] = g_h1[(size_t)n*DD + j];
        __syncthreads();
        float acc = sb[j];
        #pragma unroll 8
        for (int i = 0; i < DD; i++) acc = fmaf(sh[p][g][i], sW[i*FF + j], acc);
        g_u[(size_t)n*FF + j] = fmaxf(acc, 0.0f);
        p ^= 1;
    }
}

// ---------------- FFN fc2 + residual + LN2 ----------------
__global__ void __launch_bounds__(256) ffn2_kernel(
        const float* __restrict__ W2,
        const float* __restrict__ b2,
        const float* __restrict__ lg,
        const float* __restrict__ lb,
        float* __restrict__ outp){
    __shared__ float sW[FF*DD];   // 32 KB
    __shared__ float sb[DD], sgm[DD], sbn[DD];
    __shared__ float su[2][4][FF];
    __shared__ float xch[2][4][2][2];
    for (int i = threadIdx.x; i < FF*DD; i += 256) sW[i] = W2[i];
    if (threadIdx.x < DD){
        sb[threadIdx.x]  = b2[threadIdx.x];
        sgm[threadIdx.x] = lg[threadIdx.x];
        sbn[threadIdx.x] = lb[threadIdx.x];
    }
    __syncthreads();
    const int j = threadIdx.x & 63;
    const int g = threadIdx.x >> 6;
    const int w = (threadIdx.x >> 5) & 1;
    const int lane = threadIdx.x & 31;
    int p = 0;
    for (int n0 = blockIdx.x*4; n0 < NN; n0 += gridDim.x*4){
        const int n = n0 + g;
        su[p][g][j]      = g_u[(size_t)n*FF + j];
        su[p][g][j + DD] = g_u[(size_t)n*FF + DD + j];
        __syncthreads();
        float o = 0.f;
        #pragma unroll 8
        for (int i = 0; i < FF; i++) o = fmaf(su[p][g][i], sW[i*DD + j], o);
        o += sb[j] + g_h1[(size_t)n*DD + j];
        float s1 = o, s2 = o*o;
        #pragma unroll
        for (int off = 16; off > 0; off >>= 1){
            s1 += __shfl_xor_sync(0xffffffffu, s1, off);
            s2 += __shfl_xor_sync(0xffffffffu, s2, off);
        }
        if (lane == 0){ xch[p][g][w][0] = s1; xch[p][g][w][1] = s2; }
        __syncthreads();
        float m1 = xch[p][g][0][0] + xch[p][g][1][0];
        float m2 = xch[p][g][0][1] + xch[p][g][1][1];
        float mu  = m1 * (1.0f/DD);
        float var = m2 * (1.0f/DD) - mu*mu;
        float inv = rsqrtf(var + 1e-5f);
        outp[(size_t)n*DD + j] = (o - mu) * inv * sgm[j] + sbn[j];
        p ^= 1;
    }
}

// ---------------- host launcher ----------------
extern "C" void kernel_launch(void* const* d_in, const int* in_sizes, int n_in,
                              void* d_out, int out_size){
    const float* x   = (const float*)d_in[0];
    const float* ea  = (const float*)d_in[1];
    const void*  ei  = d_in[2];
    const float* WQ  = (const float*)d_in[3];
    const float* WK  = (const float*)d_in[4];
    const float* WE  = (const float*)d_in[5];
    const float* WV  = (const float*)d_in[6];
    const float* WO  = (const float*)d_in[7];
    const float* bO  = (const float*)d_in[8];
    const float* g1  = (const float*)d_in[9];
    const float* b1n = (const float*)d_in[10];
    const float* W1  = (const float*)d_in[11];
    const float* b1  = (const float*)d_in[12];
    const float* W2  = (const float*)d_in[13];
    const float* b2  = (const float*)d_in[14];
    const float* g2  = (const float*)d_in[15];
    const float* b2n = (const float*)d_in[16];
    float* outp = (float*)d_out;

    float* p_h = nullptr;
    cudaGetSymbolAddress((void**)&p_h, g_h);

    const int gemm_smem = (128*ASTR + 2*64*BSTR) * (int)sizeof(float);  // ~70 KB
    cudaFuncSetAttribute(edge_fused_kernel,
                         cudaFuncAttributeMaxDynamicSharedMemorySize, gemm_smem);
    cudaFuncSetAttribute(qkv_mma_kernel,
                         cudaFuncAttributeMaxDynamicSharedMemorySize, gemm_smem);

    detect_idx_kernel<<<1, 1>>>((const long long*)ei);

    const int edge_blocks = EE / 128;          // 6250 (exact)
    const int qkv_blocks  = (NN + 127) / 128;  // 391

    for (int l = 0; l < LL; l++){
        const float* hin  = (l == 0) ? x : (const float*)p_h;
        float*       hout = (l == LL-1) ? outp : p_h;
        zero_kernel<<<(NN*DD/4 + 255)/256, 256>>>();
        qkv_mma_kernel<<<qkv_blocks, 256, gemm_smem>>>(
            hin, WQ + l*DD*DD, WK + l*DD*DD, WV + l*DD*DD, NN);
        edge_fused_kernel<<<edge_blocks, 256, gemm_smem>>>(
            ea, WE + l*DD*DD, ei);
        combine_kernel<<<1184, 256>>>(hin, WO + l*DD*DD, bO + l*DD,
                                      g1 + l*DD, b1n + l*DD);
        ffn1_kernel<<<1184, 256>>>(W1 + l*DD*FF, b1 + l*FF);
        ffn2_kernel<<<1184, 256>>>(W2 + l*FF*DD, b2 + l*DD,
                                   g2 + l*DD, b2n + l*DD, hout);
    }
}

// round 8
// speedup vs baseline: 2.2299x; 1.3730x over previous
#include <cuda_runtime.h>
#include <cstdint>

#define NN 50000
#define EE 800000
#define DD 64
#define HH 4
#define FF 128
#define LL 2

#define ASTR 68
#define BSTR 72

// ---------------- device scratch (static, no allocation) ----------------
__device__ float g_Q[NN*DD];
__device__ float g_K[NN*DD];
__device__ float g_V[NN*DD];
__device__ float g_wV[NN*DD];
__device__ float g_Z[NN*HH];
__device__ float g_h[NN*DD];    // inter-layer h
__device__ float g_h1[NN*DD];   // post-LN1
__device__ float g_u[NN*FF];    // FFN hidden
__device__ int   g_is64;

// ---------------- tf32 helpers ----------------
__device__ __forceinline__ void split_tf32(float x, uint32_t& hi, uint32_t& lo){
    asm("cvt.rna.tf32.f32 %0, %1;" : "=r"(hi) : "f"(x));
    float r = x - __uint_as_float(hi);
    asm("cvt.rna.tf32.f32 %0, %1;" : "=r"(lo) : "f"(r));
}
__device__ __forceinline__ void mma8(float* c, const uint32_t* a, uint32_t b0, uint32_t b1){
    asm volatile(
      "mma.sync.aligned.m16n8k8.row.col.f32.tf32.tf32.f32 "
      "{%0,%1,%2,%3}, {%4,%5,%6,%7}, {%8,%9}, {%0,%1,%2,%3};"
      : "+f"(c[0]), "+f"(c[1]), "+f"(c[2]), "+f"(c[3])
      : "r"(a[0]), "r"(a[1]), "r"(a[2]), "r"(a[3]), "r"(b0), "r"(b1));
}

// ---------------- index dtype detection (int64 vs int32) ----------------
__global__ void detect_idx_kernel(const long long* __restrict__ idx){
    if (blockIdx.x == 0 && threadIdx.x == 0){
        int ok = 1;
        #pragma unroll
        for (int i = 0; i < 16; i++){
            long long v = idx[i];
            if (v < 0 || v >= NN) ok = 0;
        }
        g_is64 = ok;
    }
}

// ---------------- zero accumulators (vectorized) ----------------
__global__ void zero_kernel(){
    int i = blockIdx.x * blockDim.x + threadIdx.x;
    if (i < NN*DD/4) ((float4*)g_wV)[i] = make_float4(0.f,0.f,0.f,0.f);
    if (i < NN*HH/4) ((float4*)g_Z)[i]  = make_float4(0.f,0.f,0.f,0.f);
}

// ================= MMA tile compute: [128,64]@[64,64], 3xTF32 ============
// Accumulates into c (caller zeroes).
__device__ __forceinline__ void gemm_tile_acc(
        const float* sA, const float* sBh, const float* sBl,
        int warp, int lane, float c[8][4]){
    const int gID = lane >> 2, tig = lane & 3;
    const int wr = warp * 16;
    #pragma unroll
    for (int k = 0; k < 8; k++){
        const float* ap = sA + (wr + gID)*ASTR + k*8 + tig;
        float a0f = ap[0], a1f = ap[8*ASTR], a2f = ap[4], a3f = ap[8*ASTR + 4];
        uint32_t ah[4], al[4];
        split_tf32(a0f, ah[0], al[0]);
        split_tf32(a1f, ah[1], al[1]);
        split_tf32(a2f, ah[2], al[2]);
        split_tf32(a3f, ah[3], al[3]);
        const int brow = k*8 + tig;
        #pragma unroll
        for (int nt = 0; nt < 8; nt++){
            const int bc = nt*8 + gID;
            uint32_t bh0 = __float_as_uint(sBh[brow*BSTR + bc]);
            uint32_t bh1 = __float_as_uint(sBh[(brow+4)*BSTR + bc]);
            uint32_t bl0 = __float_as_uint(sBl[brow*BSTR + bc]);
            uint32_t bl1 = __float_as_uint(sBl[(brow+4)*BSTR + bc]);
            mma8(c[nt], ah, bh0, bh1);   // hi*hi
            mma8(c[nt], ah, bl0, bl1);   // hi*lo
            mma8(c[nt], al, bh0, bh1);   // lo*hi
        }
    }
}
__device__ __forceinline__ void zero_c(float c[8][4]){
    #pragma unroll
    for (int nt = 0; nt < 8; nt++){ c[nt][0]=c[nt][1]=c[nt][2]=c[nt][3]=0.f; }
}

__device__ __forceinline__ void gemm_store(
        float* __restrict__ C, int m0, int M, int warp, int lane, float c[8][4]){
    const int gID = lane >> 2, tig = lane & 3;
    const int r0 = m0 + warp*16 + gID;
    const int r1 = r0 + 8;
    #pragma unroll
    for (int nt = 0; nt < 8; nt++){
        const int col = nt*8 + tig*2;
        if (r0 < M) *(float2*)&C[(size_t)r0*DD + col] = make_float2(c[nt][0], c[nt][1]);
        if (r1 < M) *(float2*)&C[(size_t)r1*DD + col] = make_float2(c[nt][2], c[nt][3]);
    }
}

// stage B (64x64) as hi/lo tf32 into smem
__device__ __forceinline__ void stage_B(const float* __restrict__ B,
                                        float* sBh, float* sBl, int tid){
    for (int i = tid; i < 64*64; i += 256){
        int r = i >> 6, cc = i & 63;
        uint32_t h, l; split_tf32(B[i], h, l);
        sBh[r*BSTR + cc] = __uint_as_float(h);
        sBl[r*BSTR + cc] = __uint_as_float(l);
    }
}

// register-resident LN epilogue over 64-col rows spread across a lane-quad
__device__ __forceinline__ void ln_epilogue(
        float c[8][4], int m0, int warp, int lane,
        const float* __restrict__ resid, const float* __restrict__ bias,
        const float* __restrict__ lg, const float* __restrict__ lb,
        float* __restrict__ out){
    const int gID = lane >> 2, tig = lane & 3;
    const int r0 = m0 + warp*16 + gID;
    const int r1 = r0 + 8;
    const int ra = (r0 < NN) ? r0 : NN-1;
    const int rb = (r1 < NN) ? r1 : NN-1;
    float s1a=0.f, s2a=0.f, s1b=0.f, s2b=0.f;
    #pragma unroll
    for (int nt = 0; nt < 8; nt++){
        const int col = nt*8 + tig*2;
        float2 bb = *(const float2*)&bias[col];
        float2 ha = *(const float2*)&resid[(size_t)ra*DD + col];
        float2 hb = *(const float2*)&resid[(size_t)rb*DD + col];
        c[nt][0] += bb.x + ha.x;  c[nt][1] += bb.y + ha.y;
        c[nt][2] += bb.x + hb.x;  c[nt][3] += bb.y + hb.y;
        s1a += c[nt][0] + c[nt][1];
        s2a += c[nt][0]*c[nt][0] + c[nt][1]*c[nt][1];
        s1b += c[nt][2] + c[nt][3];
        s2b += c[nt][2]*c[nt][2] + c[nt][3]*c[nt][3];
    }
    #pragma unroll
    for (int off = 1; off <= 2; off <<= 1){
        s1a += __shfl_xor_sync(0xffffffffu, s1a, off);
        s2a += __shfl_xor_sync(0xffffffffu, s2a, off);
        s1b += __shfl_xor_sync(0xffffffffu, s1b, off);
        s2b += __shfl_xor_sync(0xffffffffu, s2b, off);
    }
    const float mua = s1a*(1.0f/DD), vara = s2a*(1.0f/DD) - mua*mua;
    const float mub = s1b*(1.0f/DD), varb = s2b*(1.0f/DD) - mub*mub;
    const float inva = rsqrtf(vara + 1e-5f);
    const float invb = rsqrtf(varb + 1e-5f);
    #pragma unroll
    for (int nt = 0; nt < 8; nt++){
        const int col = nt*8 + tig*2;
        float2 gg = *(const float2*)&lg[col];
        float2 bb = *(const float2*)&lb[col];
        if (r0 < NN) *(float2*)&out[(size_t)r0*DD + col] =
            make_float2((c[nt][0]-mua)*inva*gg.x + bb.x,
                        (c[nt][1]-mua)*inva*gg.y + bb.y);
        if (r1 < NN) *(float2*)&out[(size_t)r1*DD + col] =
            make_float2((c[nt][2]-mub)*invb*gg.x + bb.x,
                        (c[nt][3]-mub)*invb*gg.y + bb.y);
    }
}

// ========== FUSED: Eh = edge_attr@WE, then score + scatter (no g_Eh) =====
__global__ void __launch_bounds__(256) edge_fused_kernel(
        const float* __restrict__ A,        // edge_attr
        const float* __restrict__ B,        // WE
        const void*  __restrict__ eidx){
    extern __shared__ float sm[];
    float* sA  = sm;                    // 128 x ASTR (edge_attr, later Eh)
    float* sBh = sm + 128*ASTR;         // 64 x BSTR
    float* sBl = sBh + 64*BSTR;
    const int tid = threadIdx.x;
    const int m0 = blockIdx.x * 128;    // EE % 128 == 0: no tail
    for (int i = tid; i < 128*64; i += 256){
        int r = i >> 6, cc = i & 63;
        sA[r*ASTR + cc] = A[(size_t)(m0+r)*DD + cc];
    }
    stage_B(B, sBh, sBl, tid);
    __syncthreads();
    const int warp = tid >> 5, lane = tid & 31;
    float c[8][4];
    zero_c(c);
    gemm_tile_acc(sA, sBh, sBl, warp, lane, c);
    __syncthreads();   // done reading sA (edge_attr); safe to overwrite with Eh
    {
        const int gID = lane >> 2, tig = lane & 3;
        const int r0 = warp*16 + gID;
        const int r1 = r0 + 8;
        #pragma unroll
        for (int nt = 0; nt < 8; nt++){
            const int col = nt*8 + tig*2;
            *(float2*)&sA[r0*ASTR + col] = make_float2(c[nt][0], c[nt][1]);
            *(float2*)&sA[r1*ASTR + col] = make_float2(c[nt][2], c[nt][3]);
        }
    }
    __syncthreads();
    // ---- epilogue: 16 threads/edge, 8 iterations over 128 edges ----
    const int is64 = g_is64;
    const long long* p64 = (const long long*)eidx;
    const int*       p32 = (const int*)eidx;
    const int t  = tid & 15;
    const int g  = tid >> 4;
    const int t4 = t * 4;
    int srcs[8], dsts[8];
    #pragma unroll
    for (int it = 0; it < 8; it++){
        const int e = m0 + it*16 + g;
        if (is64){ srcs[it] = (int)p64[e]; dsts[it] = (int)p64[EE + e]; }
        else     { srcs[it] = p32[e];      dsts[it] = p32[EE + e]; }
    }
    #pragma unroll
    for (int it = 0; it < 8; it++){
        const int le  = it*16 + g;
        const int src = srcs[it], dst = dsts[it];
        float4 eh = *(const float4*)&sA[le*ASTR + t4];
        float4 kk = *(const float4*)(g_K + (size_t)src*DD + t4);
        float4 qq = *(const float4*)(g_Q + (size_t)dst*DD + t4);
        float4 vv = *(const float4*)(g_V + (size_t)src*DD + t4);
        float s = kk.x*qq.x*eh.x + kk.y*qq.y*eh.y + kk.z*qq.z*eh.z + kk.w*qq.w*eh.w;
        s += __shfl_xor_sync(0xffffffffu, s, 1);
        s += __shfl_xor_sync(0xffffffffu, s, 2);
        s *= 0.25f;                        // 1/sqrt(16)
        s  = fminf(5.0f, fmaxf(-5.0f, s));
        float sc = expf(s);
        float* wb = g_wV + (size_t)dst*DD + t4;
        asm volatile("red.global.add.v4.f32 [%0], {%1, %2, %3, %4};"
                     :: "l"(wb), "f"(vv.x*sc), "f"(vv.y*sc), "f"(vv.z*sc), "f"(vv.w*sc)
                     : "memory");
        if ((t & 3) == 0){
            asm volatile("red.global.add.f32 [%0], %1;"
                         :: "l"(g_Z + (size_t)dst*HH + (t >> 2)), "f"(sc)
                         : "memory");
        }
    }
}

// Q,K,V = h @ {WQ,WK,WV}  (shared A tile, loop over 3 weights)
__global__ void __launch_bounds__(256) qkv_mma_kernel(
        const float* __restrict__ A,
        const float* __restrict__ WQ, const float* __restrict__ WK,
        const float* __restrict__ WV, int M){
    extern __shared__ float sm[];
    float* sA  = sm;
    float* sBh = sm + 128*ASTR;
    float* sBl = sBh + 64*BSTR;
    const int tid = threadIdx.x;
    const int m0 = blockIdx.x * 128;
    for (int i = tid; i < 128*64; i += 256){
        int r = i >> 6, cc = i & 63;
        float v = (m0 + r < M) ? A[(size_t)(m0+r)*DD + cc] : 0.f;
        sA[r*ASTR + cc] = v;
    }
    const int warp = tid >> 5, lane = tid & 31;
    #pragma unroll
    for (int w = 0; w < 3; w++){
        const float* B = (w == 0) ? WQ : (w == 1) ? WK : WV;
        float* C = (w == 0) ? g_Q : (w == 1) ? g_K : g_V;
        __syncthreads();
        stage_B(B, sBh, sBl, tid);
        __syncthreads();
        float c[8][4];
        zero_c(c);
        gemm_tile_acc(sA, sBh, sBl, warp, lane, c);
        gemm_store(C, m0, M, warp, lane, c);
    }
}

// ---- combine: h_attn = wV/Z; h1 = LN(h + h_attn@WO + bO), MMA + reg-LN ----
__global__ void __launch_bounds__(256) combine_mma_kernel(
        const float* __restrict__ h_in,
        const float* __restrict__ WO,
        const float* __restrict__ bO,
        const float* __restrict__ lg,
        const float* __restrict__ lb){
    extern __shared__ float sm[];
    float* sA  = sm;
    float* sBh = sm + 128*ASTR;
    float* sBl = sBh + 64*BSTR;
    const int tid = threadIdx.x;
    const int m0 = blockIdx.x * 128;
    for (int i = tid; i < 128*64; i += 256){
        int r = i >> 6, cc = i & 63;
        int n = m0 + r; if (n >= NN) n = NN-1;
        float z = g_Z[n*HH + (cc >> 4)];
        sA[r*ASTR + cc] = g_wV[(size_t)n*DD + cc] / (z + 1e-6f);
    }
    stage_B(WO, sBh, sBl, tid);
    __syncthreads();
    const int warp = tid >> 5, lane = tid & 31;
    float c[8][4];
    zero_c(c);
    gemm_tile_acc(sA, sBh, sBl, warp, lane, c);
    ln_epilogue(c, m0, warp, lane, h_in, bO, lg, lb, g_h1);
}

// ---- FFN fc1: u = relu(h1@W1 + b1), two 64-col halves of W1 ----
__global__ void __launch_bounds__(256) ffn1_mma_kernel(
        const float* __restrict__ W1,
        const float* __restrict__ b1){
    extern __shared__ float sm[];
    float* sA  = sm;
    float* sBh = sm + 128*ASTR;
    float* sBl = sBh + 64*BSTR;
    const int tid = threadIdx.x;
    const int m0 = blockIdx.x * 128;
    for (int i = tid; i < 128*64; i += 256){
        int r = i >> 6, cc = i & 63;
        int n = m0 + r; if (n >= NN) n = NN-1;
        sA[r*ASTR + cc] = g_h1[(size_t)n*DD + cc];
    }
    const int warp = tid >> 5, lane = tid & 31;
    const int gID = lane >> 2, tig = lane & 3;
    #pragma unroll
    for (int w = 0; w < 2; w++){
        __syncthreads();
        // stage W1 half: rows k=0..63, cols w*64..w*64+63
        for (int i = tid; i < 64*64; i += 256){
            int r = i >> 6, cc = i & 63;
            uint32_t h, l; split_tf32(W1[r*FF + w*64 + cc], h, l);
            sBh[r*BSTR + cc] = __uint_as_float(h);
            sBl[r*BSTR + cc] = __uint_as_float(l);
        }
        __syncthreads();
        float c[8][4];
        zero_c(c);
        gemm_tile_acc(sA, sBh, sBl, warp, lane, c);
        const int r0 = m0 + warp*16 + gID;
        const int r1 = r0 + 8;
        #pragma unroll
        for (int nt = 0; nt < 8; nt++){
            const int col = w*64 + nt*8 + tig*2;
            float2 bb = *(const float2*)&b1[col];
            if (r0 < NN) *(float2*)&g_u[(size_t)r0*FF + col] =
                make_float2(fmaxf(c[nt][0]+bb.x, 0.f), fmaxf(c[nt][1]+bb.y, 0.f));
            if (r1 < NN) *(float2*)&g_u[(size_t)r1*FF + col] =
                make_float2(fmaxf(c[nt][2]+bb.x, 0.f), fmaxf(c[nt][3]+bb.y, 0.f));
        }
    }
}

// ---- FFN fc2 + residual + LN2: k=128 via two 64-k chunks, reg-LN ----
__global__ void __launch_bounds__(256) ffn2_mma_kernel(
        const float* __restrict__ W2,
        const float* __restrict__ b2,
        const float* __restrict__ lg,
        const float* __restrict__ lb,
        float* __restrict__ outp){
    extern __shared__ float sm[];
    float* sA  = sm;
    float* sBh = sm + 128*ASTR;
    float* sBl = sBh + 64*BSTR;
    const int tid = threadIdx.x;
    const int m0 = blockIdx.x * 128;
    const int warp = tid >> 5, lane = tid & 31;
    float c[8][4];
    zero_c(c);
    #pragma unroll
    for (int kc = 0; kc < 2; kc++){
        __syncthreads();   // protect prior chunk's smem reads
        for (int i = tid; i < 128*64; i += 256){
            int r = i >> 6, cc = i & 63;
            int n = m0 + r; if (n >= NN) n = NN-1;
            sA[r*ASTR + cc] = g_u[(size_t)n*FF + kc*64 + cc];
        }
        for (int i = tid; i < 64*64; i += 256){
            int r = i >> 6, cc = i & 63;
            uint32_t h, l; split_tf32(W2[(kc*64 + r)*DD + cc], h, l);
            sBh[r*BSTR + cc] = __uint_as_float(h);
            sBl[r*BSTR + cc] = __uint_as_float(l);
        }
        __syncthreads();
        gemm_tile_acc(sA, sBh, sBl, warp, lane, c);
    }
    ln_epilogue(c, m0, warp, lane, g_h1, b2, lg, lb, outp);
}

// ---------------- host launcher ----------------
extern "C" void kernel_launch(void* const* d_in, const int* in_sizes, int n_in,
                              void* d_out, int out_size){
    const float* x   = (const float*)d_in[0];
    const float* ea  = (const float*)d_in[1];
    const void*  ei  = d_in[2];
    const float* WQ  = (const float*)d_in[3];
    const float* WK  = (const float*)d_in[4];
    const float* WE  = (const float*)d_in[5];
    const float* WV  = (const float*)d_in[6];
    const float* WO  = (const float*)d_in[7];
    const float* bO  = (const float*)d_in[8];
    const float* g1  = (const float*)d_in[9];
    const float* b1n = (const float*)d_in[10];
    const float* W1  = (const float*)d_in[11];
    const float* b1  = (const float*)d_in[12];
    const float* W2  = (const float*)d_in[13];
    const float* b2  = (const float*)d_in[14];
    const float* g2  = (const float*)d_in[15];
    const float* b2n = (const float*)d_in[16];
    float* outp = (float*)d_out;

    float* p_h = nullptr;
    cudaGetSymbolAddress((void**)&p_h, g_h);

    const int gemm_smem = (128*ASTR + 2*64*BSTR) * (int)sizeof(float);  // ~70 KB
    cudaFuncSetAttribute(edge_fused_kernel,
                         cudaFuncAttributeMaxDynamicSharedMemorySize, gemm_smem);
    cudaFuncSetAttribute(qkv_mma_kernel,
                         cudaFuncAttributeMaxDynamicSharedMemorySize, gemm_smem);
    cudaFuncSetAttribute(combine_mma_kernel,
                         cudaFuncAttributeMaxDynamicSharedMemorySize, gemm_smem);
    cudaFuncSetAttribute(ffn1_mma_kernel,
                         cudaFuncAttributeMaxDynamicSharedMemorySize, gemm_smem);
    cudaFuncSetAttribute(ffn2_mma_kernel,
                         cudaFuncAttributeMaxDynamicSharedMemorySize, gemm_smem);

    detect_idx_kernel<<<1, 1>>>((const long long*)ei);

    const int edge_blocks = EE / 128;          // 6250 (exact)
    const int node_blocks = (NN + 127) / 128;  // 391

    for (int l = 0; l < LL; l++){
        const float* hin  = (l == 0) ? x : (const float*)p_h;
        float*       hout = (l == LL-1) ? outp : p_h;
        zero_kernel<<<(NN*DD/4 + 255)/256, 256>>>();
        qkv_mma_kernel<<<node_blocks, 256, gemm_smem>>>(
            hin, WQ + l*DD*DD, WK + l*DD*DD, WV + l*DD*DD, NN);
        edge_fused_kernel<<<edge_blocks, 256, gemm_smem>>>(
            ea, WE + l*DD*DD, ei);
        combine_mma_kernel<<<node_blocks, 256, gemm_smem>>>(
            hin, WO + l*DD*DD, bO + l*DD, g1 + l*DD, b1n + l*DD);
        ffn1_mma_kernel<<<node_blocks, 256, gemm_smem>>>(
            W1 + l*DD*FF, b1 + l*FF);
        ffn2_mma_kernel<<<node_blocks, 256, gemm_smem>>>(
            W2 + l*FF*DD, b2 + l*DD, g2 + l*DD, b2n + l*DD, hout);
    }
}